// round 2
// baseline (speedup 1.0000x reference)
#include <cuda_runtime.h>
#include <math.h>

#define B_     64
#define T_     128
#define EMB_   256
#define UNITS_ 1024
#define U3_    3072
#define M_     (B_ * T_)   // 8192

// Scratch (device globals: the sanctioned alloc-free workaround)
__device__ float g_xin[M_ * U3_];        // [B*T, 3*UNITS] input projections (+b0)
__device__ float g_h[2][B_ * UNITS_];    // ping-pong hidden state

// ---------------------------------------------------------------------------
// init hidden state buffer
// ---------------------------------------------------------------------------
__global__ void init_h_kernel(const float* __restrict__ hidden) {
    int i = blockIdx.x * blockDim.x + threadIdx.x;
    if (i < B_ * UNITS_) g_h[0][i] = hidden[i];
}

// ---------------------------------------------------------------------------
// Phase A: xin = E[x] @ W + b0
// Block tile 128(M) x 64(N), KT=32, K=256. 256 threads, thread tile 8x4.
// ---------------------------------------------------------------------------
__global__ void xin_gemm_kernel(const int* __restrict__ x,
                                const float* __restrict__ E,
                                const float* __restrict__ W,
                                const float* __restrict__ bias) {
    __shared__ float As[32][132];  // [k][m], pad to 132 (16B-aligned rows)
    __shared__ float Bs[32][68];   // [k][n], pad to 68
    __shared__ int rows[128];

    const int m0 = blockIdx.y * 128;
    const int n0 = blockIdx.x * 64;
    const int tid = threadIdx.x;         // 256
    const int tx = tid & 15;             // 16 col groups
    const int ty = tid >> 4;             // 16 row groups

    if (tid < 128) rows[tid] = x[m0 + tid];
    __syncthreads();

    float acc[8][4];
#pragma unroll
    for (int i = 0; i < 8; i++)
#pragma unroll
        for (int j = 0; j < 4; j++) acc[i][j] = 0.0f;

    for (int k0 = 0; k0 < EMB_; k0 += 32) {
        // Load A tile: 128 m x 32 k (coalesced over k), store transposed [k][m]
#pragma unroll
        for (int i = 0; i < 16; i++) {
            int idx = i * 256 + tid;
            int k = idx & 31, m = idx >> 5;
            As[k][m] = E[rows[m] * EMB_ + k0 + k];
        }
        // Load B tile: 32 k x 64 n (coalesced over n)
#pragma unroll
        for (int i = 0; i < 8; i++) {
            int idx = i * 256 + tid;
            int n = idx & 63, k = idx >> 6;
            Bs[k][n] = W[(k0 + k) * U3_ + n0 + n];
        }
        __syncthreads();

#pragma unroll
        for (int k = 0; k < 32; k++) {
            float a[8], bv[4];
#pragma unroll
            for (int i = 0; i < 8; i++) a[i] = As[k][ty * 8 + i];
#pragma unroll
            for (int j = 0; j < 4; j++) bv[j] = Bs[k][tx * 4 + j];
#pragma unroll
            for (int i = 0; i < 8; i++)
#pragma unroll
                for (int j = 0; j < 4; j++)
                    acc[i][j] = fmaf(a[i], bv[j], acc[i][j]);
        }
        __syncthreads();
    }

#pragma unroll
    for (int i = 0; i < 8; i++) {
        int m = m0 + ty * 8 + i;
#pragma unroll
        for (int j = 0; j < 4; j++) {
            int n = n0 + tx * 4 + j;
            g_xin[m * U3_ + n] = acc[i][j] + bias[n];  // + b[0]
        }
    }
}

// ---------------------------------------------------------------------------
// Phase B: one GRU step, fully fused.
// Grid: 128 blocks, each owns 8 UNITS columns (all 3 gate segments).
// 256 threads: warp w -> column c=w; lane l -> rows l and l+32.
// rec = h @ U (+b1 at epilogue), gates, h_new, output write.
// ---------------------------------------------------------------------------
__device__ __forceinline__ float sigmoidf_(float v) {
    return 1.0f / (1.0f + expf(-v));
}

__global__ void gru_step_kernel(const float* __restrict__ Umat,
                                const float* __restrict__ bias,
                                float* __restrict__ out, int t) {
    __shared__ float hs[64][65];      // [k][m], pad 65 -> conflict-free both ways
    __shared__ float Us[3][64][8];    // [seg][k][c]

    const int cur = t & 1;
    const int nxt = cur ^ 1;
    const float* __restrict__ h = g_h[cur];
    float* __restrict__ hnew = g_h[nxt];

    const int n0 = blockIdx.x * 8;
    const int tid = threadIdx.x;     // 256
    const int c = tid >> 5;          // warp id = column within tile
    const int l = tid & 31;          // lane -> rows l, l+32

    float az0 = 0.f, az1 = 0.f, ar0 = 0.f, ar1 = 0.f, ah0 = 0.f, ah1 = 0.f;

    for (int k0 = 0; k0 < UNITS_; k0 += 64) {
        // Stage h tile: 64 m x 64 k, coalesced over k, store [k][m]
#pragma unroll
        for (int i = 0; i < 16; i++) {
            int idx = i * 256 + tid;
            int k = idx & 63, m = idx >> 6;
            hs[k][m] = h[m * UNITS_ + k0 + k];
        }
        // Stage U tile: 3 seg x 64 k x 8 c
#pragma unroll
        for (int i = 0; i < 6; i++) {
            int idx = i * 256 + tid;
            int cc = idx & 7, kk = (idx >> 3) & 63, s = idx >> 9;
            Us[s][kk][cc] = Umat[(k0 + kk) * U3_ + s * UNITS_ + n0 + cc];
        }
        __syncthreads();

#pragma unroll
        for (int k = 0; k < 64; k++) {
            float h0 = hs[k][l];
            float h1 = hs[k][l + 32];
            float uz = Us[0][k][c];
            float ur = Us[1][k][c];
            float uh = Us[2][k][c];
            az0 = fmaf(h0, uz, az0); az1 = fmaf(h1, uz, az1);
            ar0 = fmaf(h0, ur, ar0); ar1 = fmaf(h1, ur, ar1);
            ah0 = fmaf(h0, uh, ah0); ah1 = fmaf(h1, uh, ah1);
        }
        __syncthreads();
    }

    const int n = n0 + c;
    const float bz = bias[U3_ + n];
    const float br = bias[U3_ + UNITS_ + n];
    const float bh = bias[U3_ + 2 * UNITS_ + n];

#pragma unroll
    for (int half = 0; half < 2; half++) {
        int m = l + half * 32;                      // batch index
        float az = half ? az1 : az0;
        float ar = half ? ar1 : ar0;
        float ah = half ? ah1 : ah0;

        const float* xrow = &g_xin[(m * T_ + t) * U3_];
        float xz = xrow[n];
        float xr = xrow[UNITS_ + n];
        float xh = xrow[2 * UNITS_ + n];

        float z = sigmoidf_(xz + az + bz);
        float r = sigmoidf_(xr + ar + br);
        float hh = tanhf(xh + r * (ah + bh));
        float hp = h[m * UNITS_ + n];
        float hn = z * hp + (1.0f - z) * hh;

        hnew[m * UNITS_ + n] = hn;
        out[(m * T_ + t) * UNITS_ + n] = hn;
        if (t == T_ - 1) {
            // final state block appended after outputs
            out[M_ * UNITS_ + m * UNITS_ + n] = hn;
        }
    }
}

// ---------------------------------------------------------------------------
// Launch: init + time-parallel GEMM + 128 sequential step kernels.
// All on the default stream (serialized, graph-capturable).
// ---------------------------------------------------------------------------
extern "C" void kernel_launch(void* const* d_in, const int* in_sizes, int n_in,
                              void* d_out, int out_size) {
    const int*   x      = (const int*)d_in[0];
    const float* hidden = (const float*)d_in[1];
    const float* E      = (const float*)d_in[2];
    const float* W      = (const float*)d_in[3];
    const float* Umat   = (const float*)d_in[4];
    const float* bias   = (const float*)d_in[5];
    float* out = (float*)d_out;

    init_h_kernel<<<(B_ * UNITS_ + 255) / 256, 256>>>(hidden);

    dim3 gridA(U3_ / 64, M_ / 128);   // (48, 64)
    xin_gemm_kernel<<<gridA, 256>>>(x, E, W, bias);

    for (int t = 0; t < T_; t++) {
        gru_step_kernel<<<UNITS_ / 8, 256>>>(Umat, bias, out, t);
    }
}

// round 3
// speedup vs baseline: 1.0036x; 1.0036x over previous
#include <cuda_runtime.h>
#include <math.h>

#define B_     64
#define T_     128
#define EMB_   256
#define UNITS_ 1024
#define U3_    3072
#define M_     (B_ * T_)   // 8192

// Scratch (device globals: the sanctioned alloc-free workaround)
__device__ float g_xin[M_ * U3_];        // [B*T, 3*UNITS] input projections (+b0)
__device__ float g_h[2][B_ * UNITS_];    // ping-pong hidden state

// ---------------------------------------------------------------------------
// init hidden state buffer
// ---------------------------------------------------------------------------
__global__ void init_h_kernel(const float* __restrict__ hidden) {
    int i = blockIdx.x * blockDim.x + threadIdx.x;
    if (i < B_ * UNITS_) g_h[0][i] = hidden[i];
}

// ---------------------------------------------------------------------------
// Phase A: xin = E[x] @ W + b0
// Block tile 128(M) x 64(N), KT=32, K=256. 256 threads, thread tile 8x4.
// ---------------------------------------------------------------------------
__global__ void xin_gemm_kernel(const int* __restrict__ x,
                                const float* __restrict__ E,
                                const float* __restrict__ W,
                                const float* __restrict__ bias) {
    __shared__ float As[32][132];  // [k][m], pad to 132 (16B-aligned rows)
    __shared__ float Bs[32][68];   // [k][n], pad to 68
    __shared__ int rows[128];

    const int m0 = blockIdx.y * 128;
    const int n0 = blockIdx.x * 64;
    const int tid = threadIdx.x;         // 256
    const int tx = tid & 15;             // 16 col groups
    const int ty = tid >> 4;             // 16 row groups

    if (tid < 128) rows[tid] = x[m0 + tid];
    __syncthreads();

    float acc[8][4];
#pragma unroll
    for (int i = 0; i < 8; i++)
#pragma unroll
        for (int j = 0; j < 4; j++) acc[i][j] = 0.0f;

    for (int k0 = 0; k0 < EMB_; k0 += 32) {
        // Load A tile: 128 m x 32 k (coalesced over k), store transposed [k][m]
#pragma unroll
        for (int i = 0; i < 16; i++) {
            int idx = i * 256 + tid;
            int k = idx & 31, m = idx >> 5;
            As[k][m] = E[rows[m] * EMB_ + k0 + k];
        }
        // Load B tile: 32 k x 64 n (coalesced over n)
#pragma unroll
        for (int i = 0; i < 8; i++) {
            int idx = i * 256 + tid;
            int n = idx & 63, k = idx >> 6;
            Bs[k][n] = W[(k0 + k) * U3_ + n0 + n];
        }
        __syncthreads();

#pragma unroll
        for (int k = 0; k < 32; k++) {
            float a[8], bv[4];
#pragma unroll
            for (int i = 0; i < 8; i++) a[i] = As[k][ty * 8 + i];
#pragma unroll
            for (int j = 0; j < 4; j++) bv[j] = Bs[k][tx * 4 + j];
#pragma unroll
            for (int i = 0; i < 8; i++)
#pragma unroll
                for (int j = 0; j < 4; j++)
                    acc[i][j] = fmaf(a[i], bv[j], acc[i][j]);
        }
        __syncthreads();
    }

#pragma unroll
    for (int i = 0; i < 8; i++) {
        int m = m0 + ty * 8 + i;
#pragma unroll
        for (int j = 0; j < 4; j++) {
            int n = n0 + tx * 4 + j;
            g_xin[m * U3_ + n] = acc[i][j] + bias[n];  // + b[0]
        }
    }
}

// ---------------------------------------------------------------------------
// Phase B: one GRU step, fully fused.
// Grid: 128 blocks, each owns 8 UNITS columns (all 3 gate segments).
// 256 threads: warp w -> column c=w; lane l -> rows l and l+32.
// rec = h @ U (+b1 at epilogue), gates, h_new, output write.
// ---------------------------------------------------------------------------
__device__ __forceinline__ float sigmoidf_(float v) {
    return 1.0f / (1.0f + expf(-v));
}

__global__ void gru_step_kernel(const float* __restrict__ Umat,
                                const float* __restrict__ bias,
                                float* __restrict__ out, int t) {
    __shared__ float hs[64][65];      // [k][m], pad 65 -> conflict-free both ways
    __shared__ float Us[3][64][8];    // [seg][k][c]

    const int cur = t & 1;
    const int nxt = cur ^ 1;
    const float* __restrict__ h = g_h[cur];
    float* __restrict__ hnew = g_h[nxt];

    const int n0 = blockIdx.x * 8;
    const int tid = threadIdx.x;     // 256
    const int c = tid >> 5;          // warp id = column within tile
    const int l = tid & 31;          // lane -> rows l, l+32

    float az0 = 0.f, az1 = 0.f, ar0 = 0.f, ar1 = 0.f, ah0 = 0.f, ah1 = 0.f;

    for (int k0 = 0; k0 < UNITS_; k0 += 64) {
        // Stage h tile: 64 m x 64 k, coalesced over k, store [k][m]
#pragma unroll
        for (int i = 0; i < 16; i++) {
            int idx = i * 256 + tid;
            int k = idx & 63, m = idx >> 6;
            hs[k][m] = h[m * UNITS_ + k0 + k];
        }
        // Stage U tile: 3 seg x 64 k x 8 c
#pragma unroll
        for (int i = 0; i < 6; i++) {
            int idx = i * 256 + tid;
            int cc = idx & 7, kk = (idx >> 3) & 63, s = idx >> 9;
            Us[s][kk][cc] = Umat[(k0 + kk) * U3_ + s * UNITS_ + n0 + cc];
        }
        __syncthreads();

#pragma unroll
        for (int k = 0; k < 64; k++) {
            float h0 = hs[k][l];
            float h1 = hs[k][l + 32];
            float uz = Us[0][k][c];
            float ur = Us[1][k][c];
            float uh = Us[2][k][c];
            az0 = fmaf(h0, uz, az0); az1 = fmaf(h1, uz, az1);
            ar0 = fmaf(h0, ur, ar0); ar1 = fmaf(h1, ur, ar1);
            ah0 = fmaf(h0, uh, ah0); ah1 = fmaf(h1, uh, ah1);
        }
        __syncthreads();
    }

    const int n = n0 + c;
    const float bz = bias[U3_ + n];
    const float br = bias[U3_ + UNITS_ + n];
    const float bh = bias[U3_ + 2 * UNITS_ + n];

#pragma unroll
    for (int half = 0; half < 2; half++) {
        int m = l + half * 32;                      // batch index
        float az = half ? az1 : az0;
        float ar = half ? ar1 : ar0;
        float ah = half ? ah1 : ah0;

        const float* xrow = &g_xin[(m * T_ + t) * U3_];
        float xz = xrow[n];
        float xr = xrow[UNITS_ + n];
        float xh = xrow[2 * UNITS_ + n];

        float z = sigmoidf_(xz + az + bz);
        float r = sigmoidf_(xr + ar + br);
        float hh = tanhf(xh + r * (ah + bh));
        float hp = h[m * UNITS_ + n];
        float hn = z * hp + (1.0f - z) * hh;

        hnew[m * UNITS_ + n] = hn;
        out[(m * T_ + t) * UNITS_ + n] = hn;
        if (t == T_ - 1) {
            // final state block appended after outputs
            out[M_ * UNITS_ + m * UNITS_ + n] = hn;
        }
    }
}

// ---------------------------------------------------------------------------
// Launch: init + time-parallel GEMM + 128 sequential step kernels.
// All on the default stream (serialized, graph-capturable).
// ---------------------------------------------------------------------------
extern "C" void kernel_launch(void* const* d_in, const int* in_sizes, int n_in,
                              void* d_out, int out_size) {
    const int*   x      = (const int*)d_in[0];
    const float* hidden = (const float*)d_in[1];
    const float* E      = (const float*)d_in[2];
    const float* W      = (const float*)d_in[3];
    const float* Umat   = (const float*)d_in[4];
    const float* bias   = (const float*)d_in[5];
    float* out = (float*)d_out;

    init_h_kernel<<<(B_ * UNITS_ + 255) / 256, 256>>>(hidden);

    dim3 gridA(U3_ / 64, M_ / 128);   // (48, 64)
    xin_gemm_kernel<<<gridA, 256>>>(x, E, W, bias);

    for (int t = 0; t < T_; t++) {
        gru_step_kernel<<<UNITS_ / 8, 256>>>(Umat, bias, out, t);
    }
}

// round 5
// speedup vs baseline: 2.3324x; 2.3240x over previous
#include <cuda_runtime.h>
#include <math.h>

typedef unsigned long long ull;

#define B_     64
#define T_     128
#define EMB_   256
#define UNITS_ 1024
#define U3_    3072
#define M_     8192
#define KT     128

// smem layout (bytes) for gru_step — HSTRIDE must be a multiple of 16
// (cp.async.16 destination alignment), hence 34 float2 = 272 B per k-row.
#define HSTRIDE 272
#define HBUF    34816                  // 128 * 272
#define UOFF    69632                  // 2 * HBUF
#define UBUF    24576                  // 128 * 24 * 8
#define REDOFF  118784                 // UOFF + 2*UBUF
#define SMEMSZ  144384                 // REDOFF + 4*32*25*8

// device-global scratch (alloc-free rule)
__device__ float2 g_xin2[(size_t)T_ * 32 * U3_];      // [(t*32+pair)*3072 + col]
__device__ float2 g_hT[2][UNITS_][32];                // transposed, batch-paired h
__device__ float2 g_Uprep[(size_t)128 * UNITS_ * 24]; // per-block (u,u) packed U

__device__ __forceinline__ void fma2(ull& d, ull a, ull b) {
    asm("fma.rn.f32x2 %0, %1, %2, %0;" : "+l"(d) : "l"(a), "l"(b));
}
__device__ __forceinline__ ull lds64(unsigned a) {
    ull v; asm volatile("ld.shared.b64 %0, [%1];" : "=l"(v) : "r"(a)); return v;
}
__device__ __forceinline__ void cpa16(unsigned s, const void* g) {
    asm volatile("cp.async.ca.shared.global [%0], [%1], 16;" :: "r"(s), "l"(g));
}

__global__ void init_hT(const float* __restrict__ hidden) {
    int idx = blockIdx.x * 256 + threadIdx.x;          // 65536
    int b = idx >> 10, u = idx & 1023;
    ((float*)&g_hT[0][u][b >> 1])[b & 1] = hidden[idx];
}

// duplicate U into per-block coalesced layout: [bx][k][cs], cs=cg*6+uu*3+s
__global__ void uprep(const float* __restrict__ U) {
    int gid = blockIdx.x * 256 + threadIdx.x;          // 3145728
    int cs = gid % 24;
    int k  = (gid / 24) & 1023;
    int bx = gid / (24 * 1024);
    int cg = cs / 6, rem = cs % 6, uu = rem / 3, s = rem % 3;
    float v = U[k * U3_ + s * UNITS_ + bx * 8 + 2 * cg + uu];
    g_Uprep[gid] = make_float2(v, v);
}

// ---------------------------------------------------------------------------
// Phase A: xin = E[x] @ W + b0, rows remapped m' = t*64+b, epilogue writes
// batch-paired float2 into g_xin2.
// ---------------------------------------------------------------------------
__global__ void xin_gemm_kernel(const int* __restrict__ x,
                                const float* __restrict__ E,
                                const float* __restrict__ W,
                                const float* __restrict__ bias) {
    __shared__ float As[32][132];
    __shared__ float Bs[32][68];
    __shared__ int rows[128];

    const int m0 = blockIdx.y * 128;
    const int n0 = blockIdx.x * 64;
    const int tid = threadIdx.x;
    const int tx = tid & 15, ty = tid >> 4;

    if (tid < 128) {
        int mp = m0 + tid;                    // m' = t*64 + b
        rows[tid] = x[(mp & 63) * T_ + (mp >> 6)];
    }
    __syncthreads();

    float acc[8][4];
#pragma unroll
    for (int i = 0; i < 8; i++)
#pragma unroll
        for (int j = 0; j < 4; j++) acc[i][j] = 0.0f;

    for (int k0 = 0; k0 < EMB_; k0 += 32) {
#pragma unroll
        for (int i = 0; i < 16; i++) {
            int idx = i * 256 + tid;
            As[idx & 31][idx >> 5] = E[rows[idx >> 5] * EMB_ + k0 + (idx & 31)];
        }
#pragma unroll
        for (int i = 0; i < 8; i++) {
            int idx = i * 256 + tid;
            Bs[idx >> 6][idx & 63] = W[(k0 + (idx >> 6)) * U3_ + n0 + (idx & 63)];
        }
        __syncthreads();
#pragma unroll
        for (int k = 0; k < 32; k++) {
            float a[8], bv[4];
#pragma unroll
            for (int i = 0; i < 8; i++) a[i] = As[k][ty * 8 + i];
#pragma unroll
            for (int j = 0; j < 4; j++) bv[j] = Bs[k][tx * 4 + j];
#pragma unroll
            for (int i = 0; i < 8; i++)
#pragma unroll
                for (int j = 0; j < 4; j++)
                    acc[i][j] = fmaf(a[i], bv[j], acc[i][j]);
        }
        __syncthreads();
    }

    float b0 = bias[n0 + tx * 4 + 0], b1 = bias[n0 + tx * 4 + 1];
    float b2 = bias[n0 + tx * 4 + 2], b3 = bias[n0 + tx * 4 + 3];
#pragma unroll
    for (int a = 0; a < 4; a++) {
        int mpr = m0 + ty * 8 + 2 * a;
        int t = mpr >> 6, q = (mpr & 63) >> 1;
        float2* dst = &g_xin2[(size_t)(t * 32 + q) * U3_ + n0 + tx * 4];
        float4 v0 = make_float4(acc[2*a][0] + b0, acc[2*a+1][0] + b0,
                                acc[2*a][1] + b1, acc[2*a+1][1] + b1);
        float4 v1 = make_float4(acc[2*a][2] + b2, acc[2*a+1][2] + b2,
                                acc[2*a][3] + b3, acc[2*a+1][3] + b3);
        *reinterpret_cast<float4*>(dst) = v0;
        *reinterpret_cast<float4*>(dst + 2) = v1;
    }
}

// ---------------------------------------------------------------------------
// Phase B: fused GRU step. 128 blocks x 256 thr; block owns units n0..n0+7.
// Warp w: k in [tau*128 + w*16, +16). Thread (mg=lane>>2, cg=lane&3):
// 4 m-pairs {mg+8i} x 6 cs {cg*6+j}. FFMA2 + cp.async double buffering.
// ---------------------------------------------------------------------------
__global__ void __launch_bounds__(256, 1)
gru_step(const float* __restrict__ bias, float* __restrict__ out, int t) {
    extern __shared__ char sm[];
    const unsigned sb = (unsigned)__cvta_generic_to_shared(sm);
    const int tid = threadIdx.x;
    const int w = tid >> 5, lane = tid & 31;
    const int mg = lane >> 2, cg = lane & 3;
    const int bx = blockIdx.x;
    const int cur = t & 1, nxt = cur ^ 1;

    ull acc[4][6];
#pragma unroll
    for (int i = 0; i < 4; i++)
#pragma unroll
        for (int j = 0; j < 6; j++) acc[i][j] = 0ull;

    const char* hsrc = (const char*)&g_hT[cur][0][0];
    const char* usrc = (const char*)&g_Uprep[(size_t)bx * UNITS_ * 24];

    // stage tile 0 -> buf 0
#pragma unroll
    for (int c = 0; c < 8; c++) {
        int ch = tid + c * 256;                 // 0..2047
        cpa16(sb + (ch >> 4) * HSTRIDE + (ch & 15) * 16, hsrc + ch * 16);
    }
#pragma unroll
    for (int c = 0; c < 6; c++) {
        int ch = tid + c * 256;                 // 0..1535
        cpa16(sb + UOFF + ch * 16, usrc + ch * 16);
    }
    asm volatile("cp.async.commit_group;");

    for (int tau = 0; tau < 8; tau++) {
        if (tau < 7) {
            const int buf = (tau + 1) & 1;
            const int k0 = (tau + 1) * KT;
#pragma unroll
            for (int c = 0; c < 8; c++) {
                int ch = tid + c * 256;
                cpa16(sb + buf * HBUF + (ch >> 4) * HSTRIDE + (ch & 15) * 16,
                      hsrc + k0 * 256 + ch * 16);
            }
#pragma unroll
            for (int c = 0; c < 6; c++) {
                int ch = tid + c * 256;
                cpa16(sb + UOFF + buf * UBUF + ch * 16, usrc + k0 * 192 + ch * 16);
            }
            asm volatile("cp.async.commit_group;");
            asm volatile("cp.async.wait_group 1;");
        } else {
            asm volatile("cp.async.wait_group 0;");
        }
        __syncthreads();

        const int buf = tau & 1;
        const unsigned hb = sb + buf * HBUF + (unsigned)(w * 16) * HSTRIDE + mg * 8;
        const unsigned ub = sb + UOFF + buf * UBUF + (unsigned)((w * 16) * 24 + cg * 6) * 8;
#pragma unroll
        for (int kk = 0; kk < 16; kk++) {
            ull h0 = lds64(hb + kk * HSTRIDE);
            ull h1 = lds64(hb + kk * HSTRIDE + 64);
            ull h2 = lds64(hb + kk * HSTRIDE + 128);
            ull h3 = lds64(hb + kk * HSTRIDE + 192);
            ull u0 = lds64(ub + kk * 192);
            ull u1 = lds64(ub + kk * 192 + 8);
            ull u2 = lds64(ub + kk * 192 + 16);
            ull u3 = lds64(ub + kk * 192 + 24);
            ull u4 = lds64(ub + kk * 192 + 32);
            ull u5 = lds64(ub + kk * 192 + 40);
            fma2(acc[0][0], h0, u0); fma2(acc[0][1], h0, u1);
            fma2(acc[0][2], h0, u2); fma2(acc[0][3], h0, u3);
            fma2(acc[0][4], h0, u4); fma2(acc[0][5], h0, u5);
            fma2(acc[1][0], h1, u0); fma2(acc[1][1], h1, u1);
            fma2(acc[1][2], h1, u2); fma2(acc[1][3], h1, u3);
            fma2(acc[1][4], h1, u4); fma2(acc[1][5], h1, u5);
            fma2(acc[2][0], h2, u0); fma2(acc[2][1], h2, u1);
            fma2(acc[2][2], h2, u2); fma2(acc[2][3], h2, u3);
            fma2(acc[2][4], h2, u4); fma2(acc[2][5], h2, u5);
            fma2(acc[3][0], h3, u0); fma2(acc[3][1], h3, u1);
            fma2(acc[3][2], h3, u2); fma2(acc[3][3], h3, u3);
            fma2(acc[3][4], h3, u4); fma2(acc[3][5], h3, u5);
        }
        __syncthreads();
    }

    // cross-warp k reduction: warps 4-7 dump, warps 0-3 add, epilogue sums 4.
    float2* red = (float2*)(sm + REDOFF);
    if (w >= 4) {
#pragma unroll
        for (int i = 0; i < 4; i++)
#pragma unroll
            for (int j = 0; j < 6; j++)
                red[((w - 4) * 32 + lane) * 25 + i * 6 + j] =
                    *reinterpret_cast<float2*>(&acc[i][j]);
    }
    __syncthreads();
    if (w < 4) {
#pragma unroll
        for (int i = 0; i < 4; i++)
#pragma unroll
            for (int j = 0; j < 6; j++) {
                int s_ = (w * 32 + lane) * 25 + i * 6 + j;
                float2 o = red[s_];
                float2 a = *reinterpret_cast<float2*>(&acc[i][j]);
                a.x += o.x; a.y += o.y;
                red[s_] = a;
            }
    }
    __syncthreads();

    // epilogue: thread (w=unit 0..7, lane=pair 0..31)
    {
        const int pair = lane;
        const int i_e = pair >> 3, mg_e = pair & 7;
        const int cg_e = w >> 1, uu = w & 1;
        const int lane_src = mg_e * 4 + cg_e;
        float2 az = make_float2(0.f, 0.f), ar = az, ah = az;
#pragma unroll
        for (int w4 = 0; w4 < 4; w4++) {
            int base = (w4 * 32 + lane_src) * 25 + i_e * 6 + uu * 3;
            float2 a = red[base], b = red[base + 1], c = red[base + 2];
            az.x += a.x; az.y += a.y;
            ar.x += b.x; ar.y += b.y;
            ah.x += c.x; ah.y += c.y;
        }
        const int n = bx * 8 + w;
        const float bz = bias[U3_ + n];
        const float br = bias[U3_ + UNITS_ + n];
        const float bh = bias[U3_ + 2 * UNITS_ + n];

        const float2* xrow = &g_xin2[(size_t)(t * 32 + pair) * U3_];
        float2 xz = xrow[n];
        float2 xr = xrow[UNITS_ + n];
        float2 xh = xrow[2 * UNITS_ + n];
        float2 hp = g_hT[cur][n][pair];

        float z0 = 1.f / (1.f + expf(-(xz.x + az.x + bz)));
        float z1 = 1.f / (1.f + expf(-(xz.y + az.y + bz)));
        float r0 = 1.f / (1.f + expf(-(xr.x + ar.x + br)));
        float r1 = 1.f / (1.f + expf(-(xr.y + ar.y + br)));
        float hh0 = tanhf(xh.x + r0 * (ah.x + bh));
        float hh1 = tanhf(xh.y + r1 * (ah.y + bh));
        float hn0 = z0 * hp.x + (1.f - z0) * hh0;
        float hn1 = z1 * hp.y + (1.f - z1) * hh1;

        g_hT[nxt][n][pair] = make_float2(hn0, hn1);
        int b0 = 2 * pair, b1 = 2 * pair + 1;
        out[(size_t)(b0 * T_ + t) * UNITS_ + n] = hn0;
        out[(size_t)(b1 * T_ + t) * UNITS_ + n] = hn1;
        if (t == T_ - 1) {
            out[(size_t)M_ * UNITS_ + (size_t)b0 * UNITS_ + n] = hn0;
            out[(size_t)M_ * UNITS_ + (size_t)b1 * UNITS_ + n] = hn1;
        }
    }
}

extern "C" void kernel_launch(void* const* d_in, const int* in_sizes, int n_in,
                              void* d_out, int out_size) {
    const int*   x      = (const int*)d_in[0];
    const float* hidden = (const float*)d_in[1];
    const float* E      = (const float*)d_in[2];
    const float* W      = (const float*)d_in[3];
    const float* Umat   = (const float*)d_in[4];
    const float* bias   = (const float*)d_in[5];
    float* out = (float*)d_out;

    cudaFuncSetAttribute(gru_step, cudaFuncAttributeMaxDynamicSharedMemorySize,
                         SMEMSZ);

    init_hT<<<256, 256>>>(hidden);
    uprep<<<12288, 256>>>(Umat);

    dim3 gridA(U3_ / 64, M_ / 128);
    xin_gemm_kernel<<<gridA, 256>>>(x, E, W, bias);

    for (int t = 0; t < T_; t++) {
        gru_step<<<128, 256, SMEMSZ>>>(bias, out, t);
    }
}

// round 7
// speedup vs baseline: 2.3798x; 1.0203x over previous
#include <cuda_runtime.h>
#include <cuda_bf16.h>
#include <math.h>
#include <stdint.h>

typedef unsigned int u32;
typedef unsigned short u16;

#define B_     64
#define T_     128
#define EMB_   256
#define UNITS_ 1024
#define U3_    3072
#define M_     8192

#define NBLK   64           // scan blocks; block owns 16 units (48 gate-cols)
#define KT     64           // k per chunk
#define NCH    16           // chunks
// smem: H tiles [p][64][144B] = 2*9216; U tiles [p][48][144B] = 2*6912
#define HS_P   9216
#define US_OFF 18432
#define US_P   6912
#define BUF    32256
#define SMEMSZ 64512

// ---- device-global scratch (alloc-free rule) ----
__device__ float g_xin[(size_t)M_ * U3_];            // [(t*64+b)*3072 + n]
__device__ float g_hF[2][B_ * UNITS_];               // fp32 h ping-pong [b][u]
__device__ u16 g_Hbf[2][2][B_][UNITS_];              // [sel][pass][b][u] bf16
__device__ u16 g_Ubf[(size_t)NBLK * 2 * 48 * UNITS_];// [g][p][n=48][k] bf16

__device__ __forceinline__ u32 s2u(const void* p) {
    u32 r;
    asm("{ .reg .u64 t; cvta.to.shared.u64 t, %1; cvt.u32.u64 %0, t; }"
        : "=r"(r) : "l"(p));
    return r;
}
__device__ __forceinline__ void cpa16(u32 s, const void* g) {
    asm volatile("cp.async.ca.shared.global [%0], [%1], 16;" :: "r"(s), "l"(g));
}
__device__ __forceinline__ void ldmx4(u32 addr, u32 r[4]) {
    asm volatile("ldmatrix.sync.aligned.m8n8.x4.shared.b16 {%0,%1,%2,%3}, [%4];"
                 : "=r"(r[0]), "=r"(r[1]), "=r"(r[2]), "=r"(r[3]) : "r"(addr));
}
__device__ __forceinline__ void ldmx2(u32 addr, u32 r[2]) {
    asm volatile("ldmatrix.sync.aligned.m8n8.x2.shared.b16 {%0,%1}, [%2];"
                 : "=r"(r[0]), "=r"(r[1]) : "r"(addr));
}
__device__ __forceinline__ void mma16816(float c[4], const u32 a[4], const u32 b[2]) {
    asm volatile("mma.sync.aligned.m16n8k16.row.col.f32.bf16.bf16.f32 "
                 "{%0,%1,%2,%3}, {%4,%5,%6,%7}, {%8,%9}, {%0,%1,%2,%3};"
                 : "+f"(c[0]), "+f"(c[1]), "+f"(c[2]), "+f"(c[3])
                 : "r"(a[0]), "r"(a[1]), "r"(a[2]), "r"(a[3]),
                   "r"(b[0]), "r"(b[1]));
}

// ---------------------------------------------------------------------------
__global__ void init_h_tc(const float* __restrict__ hidden) {
    int idx = blockIdx.x * 256 + threadIdx.x;   // 65536
    int b = idx >> 10, u = idx & 1023;
    float v = hidden[idx];
    g_hF[0][idx] = v;
    __nv_bfloat16 hi = __float2bfloat16(v);
    __nv_bfloat16 lo = __float2bfloat16(v - __bfloat162float(hi));
    g_Hbf[0][0][b][u] = *(u16*)&hi;
    g_Hbf[0][1][b][u] = *(u16*)&lo;
}

// U^T per-block rows: g_Ubf[((g*2+p)*48 + n)*1024 + k], n = s*16 + ul
__global__ void uprep_bf(const float* __restrict__ U) {
    size_t idx = (size_t)blockIdx.x * 256 + threadIdx.x;  // 6,291,456
    int k = idx & 1023;
    int rest = (int)(idx >> 10);
    int n = rest % 48;
    int gp = rest / 48;
    int p = gp & 1, g = gp >> 1;
    int s = n >> 4, ul = n & 15;
    float v = U[(size_t)k * U3_ + s * UNITS_ + g * 16 + ul];
    __nv_bfloat16 hi = __float2bfloat16(v);
    __nv_bfloat16 w = p ? __float2bfloat16(v - __bfloat162float(hi)) : hi;
    g_Ubf[idx] = *(u16*)&w;
}

// ---------------------------------------------------------------------------
// Phase A: xin = E[x] @ W + b0, rows m' = t*64 + b (fp32 SIMT GEMM).
// ---------------------------------------------------------------------------
__global__ void xin_gemm_kernel(const int* __restrict__ x,
                                const float* __restrict__ E,
                                const float* __restrict__ W,
                                const float* __restrict__ bias) {
    __shared__ float As[32][132];
    __shared__ float Bs[32][68];
    __shared__ int rows[128];

    const int m0 = blockIdx.y * 128;
    const int n0 = blockIdx.x * 64;
    const int tid = threadIdx.x;
    const int tx = tid & 15, ty = tid >> 4;

    if (tid < 128) {
        int mp = m0 + tid;
        rows[tid] = x[(mp & 63) * T_ + (mp >> 6)];
    }
    __syncthreads();

    float acc[8][4];
#pragma unroll
    for (int i = 0; i < 8; i++)
#pragma unroll
        for (int j = 0; j < 4; j++) acc[i][j] = 0.0f;

    for (int k0 = 0; k0 < EMB_; k0 += 32) {
#pragma unroll
        for (int i = 0; i < 16; i++) {
            int idx = i * 256 + tid;
            As[idx & 31][idx >> 5] = E[rows[idx >> 5] * EMB_ + k0 + (idx & 31)];
        }
#pragma unroll
        for (int i = 0; i < 8; i++) {
            int idx = i * 256 + tid;
            Bs[idx >> 6][idx & 63] = W[(k0 + (idx >> 6)) * U3_ + n0 + (idx & 63)];
        }
        __syncthreads();
#pragma unroll
        for (int k = 0; k < 32; k++) {
            float a[8], bv[4];
#pragma unroll
            for (int i = 0; i < 8; i++) a[i] = As[k][ty * 8 + i];
#pragma unroll
            for (int j = 0; j < 4; j++) bv[j] = Bs[k][tx * 4 + j];
#pragma unroll
            for (int i = 0; i < 8; i++)
#pragma unroll
                for (int j = 0; j < 4; j++)
                    acc[i][j] = fmaf(a[i], bv[j], acc[i][j]);
        }
        __syncthreads();
    }

#pragma unroll
    for (int i = 0; i < 8; i++) {
        int m = m0 + ty * 8 + i;
#pragma unroll
        for (int j = 0; j < 4; j++) {
            int n = n0 + tx * 4 + j;
            g_xin[(size_t)m * U3_ + n] = acc[i][j] + bias[n];
        }
    }
}

// ---------------------------------------------------------------------------
// Phase B: mma.sync GRU step. 64 blocks x 256 thr (8 warps).
// Block g owns units [g*16, g*16+16). Warp w = (mt = w&3, nh = w>>2):
// batches [mt*16, +16), units [nh*8, +8) of the block, all 3 gates in regs.
// rec = h @ U via split-bf16 (hi*hi + hi*lo + lo*hi), fp32 accum.
// ---------------------------------------------------------------------------
__global__ void __launch_bounds__(256, 1)
gru_step_mma(const float* __restrict__ bias, float* __restrict__ out, int t) {
    extern __shared__ char sm[];
    const u32 sb = s2u(sm);
    const int tid = threadIdx.x;
    const int w = tid >> 5, lane = tid & 31;
    const int mt = w & 3, nh = w >> 2;
    const int g = blockIdx.x;
    const int cur = t & 1, nxt = cur ^ 1;

    const u16* hsrc = &g_Hbf[cur][0][0][0];              // [p][b][u]
    const u16* usrc = &g_Ubf[(size_t)g * 2 * 48 * 1024]; // [p][n][k]

    float acc[3][4];
#pragma unroll
    for (int i = 0; i < 3; i++)
#pragma unroll
        for (int j = 0; j < 4; j++) acc[i][j] = 0.0f;

    // ldmatrix source addresses (per-lane)
    const u32 a_addr0 = sb + (u32)((mt * 16 + (lane & 15)) * 144 + ((lane >> 4) * 8) * 2);
    const u32 b_addr0 = sb + US_OFF +
        (u32)((nh * 8 + (lane & 7)) * 144 + (((lane >> 3) & 1) * 8) * 2);

    // ---- staging helper (lambda-free, inline) ----
#define STAGE(cc, buf)                                                        \
    do {                                                                      \
        const int c_ = (cc);                                                  \
        const u32 d0 = sb + (buf) * BUF;                                      \
        _Pragma("unroll")                                                     \
        for (int j = 0; j < 4; j++) {            /* H: 1024 ops */            \
            int o = tid + j * 256;                                            \
            int p = o >> 9, row = (o >> 3) & 63, seg = o & 7;                 \
            cpa16(d0 + p * HS_P + row * 144 + seg * 16,                       \
                  hsrc + (size_t)p * 65536 + row * 1024 + c_ * 64 + seg * 8); \
        }                                                                     \
        _Pragma("unroll")                                                     \
        for (int j = 0; j < 3; j++) {            /* U: 768 ops */             \
            int o = tid + j * 256;                                            \
            int p = o / 384, rem = o % 384;                                   \
            int row = rem >> 3, seg = rem & 7;                                \
            cpa16(d0 + US_OFF + p * US_P + row * 144 + seg * 16,              \
                  usrc + (size_t)p * 49152 + row * 1024 + c_ * 64 + seg * 8); \
        }                                                                     \
        asm volatile("cp.async.commit_group;");                               \
    } while (0)

    STAGE(0, 0);

    for (int c = 0; c < NCH; c++) {
        if (c < NCH - 1) {
            STAGE(c + 1, (c + 1) & 1);
            asm volatile("cp.async.wait_group 1;");
        } else {
            asm volatile("cp.async.wait_group 0;");
        }
        __syncthreads();

        const u32 boff = (u32)((c & 1) * BUF);
#pragma unroll
        for (int ks = 0; ks < 4; ks++) {
            u32 ah[4], al[4];
            ldmx4(a_addr0 + boff + ks * 32, ah);
            ldmx4(a_addr0 + boff + HS_P + ks * 32, al);
#pragma unroll
            for (int gate = 0; gate < 3; gate++) {
                u32 bh[2], bl[2];
                u32 ba = b_addr0 + boff + gate * 16 * 144 + ks * 32;
                ldmx2(ba, bh);
                ldmx2(ba + US_P, bl);
                mma16816(acc[gate], ah, bh);
                mma16816(acc[gate], ah, bl);
                mma16816(acc[gate], al, bh);
            }
        }
        __syncthreads();
    }
#undef STAGE

    // ---- epilogue: fragment (i=batch-half, j=unit-parity) -> reg 2i+j ----
    const int u0 = g * 16 + nh * 8 + 2 * (lane & 3);
    const int b0 = mt * 16 + (lane >> 2);

#pragma unroll
    for (int j = 0; j < 2; j++) {
        const int u = u0 + j;
        const float bz = bias[U3_ + u];
        const float br = bias[U3_ + UNITS_ + u];
        const float bh_ = bias[U3_ + 2 * UNITS_ + u];
#pragma unroll
        for (int i = 0; i < 2; i++) {
            const int b = b0 + 8 * i;
            const int r = 2 * i + j;
            const float* xr_ = &g_xin[(size_t)(t * 64 + b) * U3_ + u];
            float xz = xr_[0], xr = xr_[UNITS_], xh = xr_[2 * UNITS_];
            float hprev = g_hF[cur][b * UNITS_ + u];

            float z = 1.f / (1.f + expf(-(xz + acc[0][r] + bz)));
            float rr = 1.f / (1.f + expf(-(xr + acc[1][r] + br)));
            float hh = tanhf(xh + rr * (acc[2][r] + bh_));
            float hn = z * hprev + (1.f - z) * hh;

            g_hF[nxt][b * UNITS_ + u] = hn;
            out[(size_t)(b * T_ + t) * UNITS_ + u] = hn;
            __nv_bfloat16 hi = __float2bfloat16(hn);
            __nv_bfloat16 lo = __float2bfloat16(hn - __bfloat162float(hi));
            g_Hbf[nxt][0][b][u] = *(u16*)&hi;
            g_Hbf[nxt][1][b][u] = *(u16*)&lo;
            if (t == T_ - 1)
                out[(size_t)M_ * UNITS_ + (size_t)b * UNITS_ + u] = hn;
        }
    }
}

extern "C" void kernel_launch(void* const* d_in, const int* in_sizes, int n_in,
                              void* d_out, int out_size) {
    const int*   x      = (const int*)d_in[0];
    const float* hidden = (const float*)d_in[1];
    const float* E      = (const float*)d_in[2];
    const float* W      = (const float*)d_in[3];
    const float* Umat   = (const float*)d_in[4];
    const float* bias   = (const float*)d_in[5];
    float* out = (float*)d_out;

    cudaFuncSetAttribute(gru_step_mma,
                         cudaFuncAttributeMaxDynamicSharedMemorySize, SMEMSZ);

    init_h_tc<<<256, 256>>>(hidden);
    uprep_bf<<<24576, 256>>>(Umat);

    dim3 gridA(U3_ / 64, M_ / 128);
    xin_gemm_kernel<<<gridA, 256>>>(x, E, W, bias);

    for (int t = 0; t < T_; t++) {
        gru_step_mma<<<NBLK, 256, SMEMSZ>>>(bias, out, t);
    }
}

// round 8
// speedup vs baseline: 2.9317x; 1.2319x over previous
#include <cuda_runtime.h>
#include <cuda_bf16.h>
#include <math.h>
#include <stdint.h>

typedef unsigned int u32;
typedef unsigned short u16;

#define B_     64
#define T_     128
#define EMB_   256
#define UNITS_ 1024
#define U3_    3072
#define M_     8192

#define NBLK2  128          // persistent scan blocks; block owns 8 units
// smem layout (bytes)
#define USTR   2064         // U row stride: 2048 data + 16 pad
#define HOFF   99072        // 48 * 2064
#define HSZ    18432        // H tile: 128 rows (2p x 64b) x 144
#define REDOFF 172800       // HOFF + 4*HSZ
#define SMEMSZ 178944       // REDOFF + 6144

// ---- device-global scratch (alloc-free rule) ----
__device__ float g_xin[(size_t)M_ * U3_];             // [(t*64+b)*3072 + n]
__device__ float g_hF[2][B_ * UNITS_];                // fp32 h ping-pong [b][u]
__device__ u16 g_Hbf[2][2][B_][UNITS_];               // [sel][pass][b][u]
__device__ u16 g_Ubf[(size_t)NBLK2 * 2 * 24 * UNITS_];// [g][p][n=24][k]
__device__ unsigned g_barcnt;
__device__ unsigned g_bargen;

__device__ __forceinline__ u32 s2u(const void* p) {
    u32 r;
    asm("{ .reg .u64 t; cvta.to.shared.u64 t, %1; cvt.u32.u64 %0, t; }"
        : "=r"(r) : "l"(p));
    return r;
}
__device__ __forceinline__ void cpa_cg(u32 s, const void* g) {
    asm volatile("cp.async.cg.shared.global [%0], [%1], 16;" :: "r"(s), "l"(g));
}
__device__ __forceinline__ void cpa_ca(u32 s, const void* g) {
    asm volatile("cp.async.ca.shared.global [%0], [%1], 16;" :: "r"(s), "l"(g));
}
__device__ __forceinline__ void ldmx4(u32 addr, u32 r[4]) {
    asm volatile("ldmatrix.sync.aligned.m8n8.x4.shared.b16 {%0,%1,%2,%3}, [%4];"
                 : "=r"(r[0]), "=r"(r[1]), "=r"(r[2]), "=r"(r[3]) : "r"(addr));
}
__device__ __forceinline__ void ldmx2(u32 addr, u32 r[2]) {
    asm volatile("ldmatrix.sync.aligned.m8n8.x2.shared.b16 {%0,%1}, [%2];"
                 : "=r"(r[0]), "=r"(r[1]) : "r"(addr));
}
__device__ __forceinline__ void mma16816(float c[4], const u32 a[4], const u32 b[2]) {
    asm volatile("mma.sync.aligned.m16n8k16.row.col.f32.bf16.bf16.f32 "
                 "{%0,%1,%2,%3}, {%4,%5,%6,%7}, {%8,%9}, {%0,%1,%2,%3};"
                 : "+f"(c[0]), "+f"(c[1]), "+f"(c[2]), "+f"(c[3])
                 : "r"(a[0]), "r"(a[1]), "r"(a[2]), "r"(a[3]),
                   "r"(b[0]), "r"(b[1]));
}

// ---------------------------------------------------------------------------
__global__ void init_h_tc(const float* __restrict__ hidden) {
    int idx = blockIdx.x * 256 + threadIdx.x;   // 65536
    if (idx == 0) { g_barcnt = 0; g_bargen = 0; }
    int b = idx >> 10, u = idx & 1023;
    float v = hidden[idx];
    g_hF[0][idx] = v;
    __nv_bfloat16 hi = __float2bfloat16(v);
    __nv_bfloat16 lo = __float2bfloat16(v - __bfloat162float(hi));
    g_Hbf[0][0][b][u] = *(u16*)&hi;
    g_Hbf[0][1][b][u] = *(u16*)&lo;
}

// U^T per-block rows: g_Ubf[((g*2+p)*24 + n)*1024 + k], n = gate*8 + ul
__global__ void uprep_bf(const float* __restrict__ U) {
    size_t idx = (size_t)blockIdx.x * 256 + threadIdx.x;  // 6,291,456
    int k = idx & 1023;
    int rest = (int)(idx >> 10);
    int n = rest % 24;
    int gp = rest / 24;
    int p = gp & 1, g = gp >> 1;
    int s = n >> 3, ul = n & 7;
    float v = U[(size_t)k * U3_ + s * UNITS_ + g * 8 + ul];
    __nv_bfloat16 hi = __float2bfloat16(v);
    __nv_bfloat16 w = p ? __float2bfloat16(v - __bfloat162float(hi)) : hi;
    g_Ubf[idx] = *(u16*)&w;
}

// ---------------------------------------------------------------------------
// Phase A: xin = E[x] @ W + b0, rows m' = t*64 + b (fp32 SIMT GEMM).
// ---------------------------------------------------------------------------
__global__ void xin_gemm_kernel(const int* __restrict__ x,
                                const float* __restrict__ E,
                                const float* __restrict__ W,
                                const float* __restrict__ bias) {
    __shared__ float As[32][132];
    __shared__ float Bs[32][68];
    __shared__ int rows[128];

    const int m0 = blockIdx.y * 128;
    const int n0 = blockIdx.x * 64;
    const int tid = threadIdx.x;
    const int tx = tid & 15, ty = tid >> 4;

    if (tid < 128) {
        int mp = m0 + tid;
        rows[tid] = x[(mp & 63) * T_ + (mp >> 6)];
    }
    __syncthreads();

    float acc[8][4];
#pragma unroll
    for (int i = 0; i < 8; i++)
#pragma unroll
        for (int j = 0; j < 4; j++) acc[i][j] = 0.0f;

    for (int k0 = 0; k0 < EMB_; k0 += 32) {
#pragma unroll
        for (int i = 0; i < 16; i++) {
            int idx = i * 256 + tid;
            As[idx & 31][idx >> 5] = E[rows[idx >> 5] * EMB_ + k0 + (idx & 31)];
        }
#pragma unroll
        for (int i = 0; i < 8; i++) {
            int idx = i * 256 + tid;
            Bs[idx >> 6][idx & 63] = W[(k0 + (idx >> 6)) * U3_ + n0 + (idx & 63)];
        }
        __syncthreads();
#pragma unroll
        for (int k = 0; k < 32; k++) {
            float a[8], bv[4];
#pragma unroll
            for (int i = 0; i < 8; i++) a[i] = As[k][ty * 8 + i];
#pragma unroll
            for (int j = 0; j < 4; j++) bv[j] = Bs[k][tx * 4 + j];
#pragma unroll
            for (int i = 0; i < 8; i++)
#pragma unroll
                for (int j = 0; j < 4; j++)
                    acc[i][j] = fmaf(a[i], bv[j], acc[i][j]);
        }
        __syncthreads();
    }

#pragma unroll
    for (int i = 0; i < 8; i++) {
        int m = m0 + ty * 8 + i;
#pragma unroll
        for (int j = 0; j < 4; j++) {
            int n = n0 + tx * 4 + j;
            g_xin[(size_t)m * U3_ + n] = acc[i][j] + bias[n];
        }
    }
}

// ---------------------------------------------------------------------------
// Persistent scan kernel: 128 blocks x 256 thr, 1 block/SM, all co-resident.
// Block g owns units [g*8, g*8+8). U slice resident in smem for all steps.
// Warp w: mt = w&3 (16 batches), gr = w>>2 (k-half: chunks gr*8..gr*8+7).
// Split-bf16 (hi*hi + hi*lo + lo*hi) mma.sync, fp32 accum, 3 gates in regs.
// Grid-wide barrier between steps (atomic + acquire spin).
// ---------------------------------------------------------------------------
__global__ void __launch_bounds__(256, 1)
gru_scan(const float* __restrict__ bias, float* __restrict__ out) {
    extern __shared__ char sm[];
    const u32 sb = s2u(sm);
    const int tid = threadIdx.x;
    const int w = tid >> 5, lane = tid & 31;
    const int mt = w & 3, gr = w >> 2;
    const int g = blockIdx.x;

    // ---- stage U slice once (48 rows x 2048 B, contiguous source) ----
    {
        const char* usrc = (const char*)g_Ubf + (size_t)g * 98304;
#pragma unroll
        for (int j = 0; j < 24; j++) {
            int o = tid + j * 256;              // 0..6143
            int row = o >> 7, seg = o & 127;
            cpa_ca(sb + row * USTR + seg * 16, usrc + (size_t)o * 16);
        }
        asm volatile("cp.async.commit_group;");
    }

    // per-lane ldmatrix base addresses
    const u32 a_off = (u32)((mt * 16 + (lane & 15)) * 144 + (lane >> 4) * 16);
    const u32 b01 = sb + (u32)(((lane >> 4) * 8 + (lane & 7)) * USTR +
                               ((lane >> 3) & 1) * 16);
    const u32 b2  = sb + (u32)((16 + (lane & 7)) * USTR + ((lane >> 3) & 1) * 16);

    const float bz  = bias[U3_ + g * 8 + 2 * (lane & 3)];
    const float bzj = bias[U3_ + g * 8 + 2 * (lane & 3) + 1];
    const float br  = bias[U3_ + UNITS_ + g * 8 + 2 * (lane & 3)];
    const float brj = bias[U3_ + UNITS_ + g * 8 + 2 * (lane & 3) + 1];
    const float bh  = bias[U3_ + 2 * UNITS_ + g * 8 + 2 * (lane & 3)];
    const float bhj = bias[U3_ + 2 * UNITS_ + g * 8 + 2 * (lane & 3) + 1];

    float* red = (float*)(sm + REDOFF);

    for (int t = 0; t < T_; t++) {
        const int cur = t & 1, nxt = cur ^ 1;
        const char* hsrc = (const char*)&g_Hbf[cur][0][0][0];

        float acc[3][4];
#pragma unroll
        for (int i = 0; i < 3; i++)
#pragma unroll
            for (int j = 0; j < 4; j++) acc[i][j] = 0.0f;

        // stage chunk 0 (both groups) into buf 0
#define STAGE_H(cc, buf)                                                      \
    do {                                                                      \
        _Pragma("unroll")                                                     \
        for (int j = 0; j < 8; j++) {                                         \
            int o = tid + j * 256;              /* 0..2047 */                 \
            int grs = o >> 10, r = (o >> 3) & 127, seg = o & 7;               \
            int cab = grs * 8 + (cc);                                         \
            cpa_cg(sb + HOFF + (grs * 2 + (buf)) * HSZ + r * 144 + seg * 16,  \
                   hsrc + ((size_t)r * 1024 + cab * 64) * 2 + seg * 16);      \
        }                                                                     \
        asm volatile("cp.async.commit_group;");                               \
    } while (0)

        STAGE_H(0, 0);

        for (int c = 0; c < 8; c++) {
            if (c < 7) {
                STAGE_H(c + 1, (c + 1) & 1);
                asm volatile("cp.async.wait_group 1;");
            } else {
                asm volatile("cp.async.wait_group 0;");
            }
            __syncthreads();

            const int cab = gr * 8 + c;
            const u32 abase = sb + HOFF + (u32)((gr * 2 + (c & 1)) * HSZ) + a_off;
            const u32 koff = (u32)(cab * 128);
#pragma unroll
            for (int ks = 0; ks < 4; ks++) {
                u32 ah[4], al[4], b4h[4], b4l[4], b2h[2], b2l[2];
                const u32 ko = koff + ks * 32;
                ldmx4(abase + ks * 32, ah);
                ldmx4(abase + 9216 + ks * 32, al);
                ldmx4(b01 + ko, b4h);
                ldmx4(b01 + 24 * USTR + ko, b4l);
                ldmx2(b2 + ko, b2h);
                ldmx2(b2 + 24 * USTR + ko, b2l);
                mma16816(acc[0], ah, b4h);     mma16816(acc[1], ah, b4h + 2);
                mma16816(acc[2], ah, b2h);
                mma16816(acc[0], ah, b4l);     mma16816(acc[1], ah, b4l + 2);
                mma16816(acc[2], ah, b2l);
                mma16816(acc[0], al, b4h);     mma16816(acc[1], al, b4h + 2);
                mma16816(acc[2], al, b2h);
            }
            __syncthreads();
        }
#undef STAGE_H

        // ---- cross-group reduction: gr1 dumps, gr0 adds ----
        if (gr == 1) {
#pragma unroll
            for (int i = 0; i < 3; i++)
#pragma unroll
                for (int j = 0; j < 4; j++)
                    red[(mt * 32 + lane) * 12 + i * 4 + j] = acc[i][j];
        }
        __syncthreads();

        if (gr == 0) {
#pragma unroll
            for (int i = 0; i < 3; i++)
#pragma unroll
                for (int j = 0; j < 4; j++)
                    acc[i][j] += red[(mt * 32 + lane) * 12 + i * 4 + j];

            // ---- epilogue: r = 2i+j -> batch mt*16+(lane>>2)+8i,
            //                 unit g*8 + 2*(lane&3)+j ----
#pragma unroll
            for (int j = 0; j < 2; j++) {
                const int u = g * 8 + 2 * (lane & 3) + j;
                const float bz_ = j ? bzj : bz;
                const float br_ = j ? brj : br;
                const float bh_ = j ? bhj : bh;
#pragma unroll
                for (int i = 0; i < 2; i++) {
                    const int b = mt * 16 + (lane >> 2) + 8 * i;
                    const int r = 2 * i + j;
                    const float* xr_ = &g_xin[(size_t)(t * 64 + b) * U3_ + u];
                    float xz = xr_[0], xr = xr_[UNITS_], xh = xr_[2 * UNITS_];
                    float hprev = g_hF[cur][b * UNITS_ + u];

                    float z = 1.f / (1.f + expf(-(xz + acc[0][r] + bz_)));
                    float rr = 1.f / (1.f + expf(-(xr + acc[1][r] + br_)));
                    float hh = tanhf(xh + rr * (acc[2][r] + bh_));
                    float hn = z * hprev + (1.f - z) * hh;

                    g_hF[nxt][b * UNITS_ + u] = hn;
                    out[(size_t)(b * T_ + t) * UNITS_ + u] = hn;
                    __nv_bfloat16 hi = __float2bfloat16(hn);
                    __nv_bfloat16 lo = __float2bfloat16(hn - __bfloat162float(hi));
                    g_Hbf[nxt][0][b][u] = *(u16*)&hi;
                    g_Hbf[nxt][1][b][u] = *(u16*)&lo;
                    if (t == T_ - 1)
                        out[(size_t)M_ * UNITS_ + (size_t)b * UNITS_ + u] = hn;
                }
            }
        }

        // ---- grid-wide barrier ----
        __threadfence();
        __syncthreads();
        if (tid == 0) {
            unsigned old = atomicAdd(&g_barcnt, 1);
            if (old == NBLK2 - 1) {
                g_barcnt = 0;
                __threadfence();
                atomicAdd(&g_bargen, 1);
            } else {
                unsigned v;
                do {
                    asm volatile("ld.acquire.gpu.global.u32 %0, [%1];"
                                 : "=r"(v) : "l"(&g_bargen));
                } while (v < (unsigned)(t + 1));
            }
        }
        __syncthreads();
    }
}

extern "C" void kernel_launch(void* const* d_in, const int* in_sizes, int n_in,
                              void* d_out, int out_size) {
    const int*   x      = (const int*)d_in[0];
    const float* hidden = (const float*)d_in[1];
    const float* E      = (const float*)d_in[2];
    const float* W      = (const float*)d_in[3];
    const float* Umat   = (const float*)d_in[4];
    const float* bias   = (const float*)d_in[5];
    float* out = (float*)d_out;

    cudaFuncSetAttribute(gru_scan,
                         cudaFuncAttributeMaxDynamicSharedMemorySize, SMEMSZ);

    init_h_tc<<<256, 256>>>(hidden);
    uprep_bf<<<24576, 256>>>(Umat);

    dim3 gridA(U3_ / 64, M_ / 128);
    xin_gemm_kernel<<<gridA, 256>>>(x, E, W, bias);

    gru_scan<<<NBLK2, 256, SMEMSZ>>>(bias, out);
}

// round 9
// speedup vs baseline: 4.4987x; 1.5345x over previous
#include <cuda_runtime.h>
#include <cuda_bf16.h>
#include <math.h>
#include <stdint.h>

typedef unsigned int u32;
typedef unsigned short u16;

#define B_     64
#define T_     128
#define EMB_   256
#define UNITS_ 1024
#define U3_    3072
#define M_     8192

#define NBLK2  128          // persistent scan blocks; block owns 8 units
// scan smem layout (bytes)
#define USTR   2064         // U row stride: 2048 data + 16 pad
#define HOFF   99072        // 48 * 2064
#define HSZ    18432        // H tile: 128 rows (2p x 64b) x 144
#define REDOFF 209664       // HOFF + 6*HSZ  (3-buffer x 2 groups)
#define SMEMSZ 215808       // REDOFF + 6144

// phase-A smem: 2 bufs x (A 256rowsx144 + B 256rowsx144)
#define ABUF   73728
#define SMEMA  147456

// ---- device-global scratch (alloc-free rule) ----
__device__ float g_xin[(size_t)M_ * U3_];             // [(t*64+b)*3072 + n]
__device__ float g_hF[2][B_ * UNITS_];                // fp32 h ping-pong [b][u]
__device__ u16 g_Hbf[2][2][B_][UNITS_];               // [sel][pass][b][u]
__device__ u16 g_Ubf[(size_t)NBLK2 * 2 * 24 * UNITS_];// [g][p][n=24][k]
__device__ u16 g_Ebf[(size_t)2 * M_ * EMB_];          // [p][m'][k] gathered emb
__device__ u16 g_Wbf[(size_t)2 * U3_ * EMB_];         // [p][n][k]
__device__ unsigned g_barcnt;
__device__ unsigned g_bargen;

__device__ __forceinline__ u32 s2u(const void* p) {
    u32 r;
    asm("{ .reg .u64 t; cvta.to.shared.u64 t, %1; cvt.u32.u64 %0, t; }"
        : "=r"(r) : "l"(p));
    return r;
}
__device__ __forceinline__ void cpa_cg(u32 s, const void* g) {
    asm volatile("cp.async.cg.shared.global [%0], [%1], 16;" :: "r"(s), "l"(g));
}
__device__ __forceinline__ void cpa_ca(u32 s, const void* g) {
    asm volatile("cp.async.ca.shared.global [%0], [%1], 16;" :: "r"(s), "l"(g));
}
__device__ __forceinline__ void ldmx4(u32 addr, u32 r[4]) {
    asm volatile("ldmatrix.sync.aligned.m8n8.x4.shared.b16 {%0,%1,%2,%3}, [%4];"
                 : "=r"(r[0]), "=r"(r[1]), "=r"(r[2]), "=r"(r[3]) : "r"(addr));
}
__device__ __forceinline__ void ldmx2(u32 addr, u32 r[2]) {
    asm volatile("ldmatrix.sync.aligned.m8n8.x2.shared.b16 {%0,%1}, [%2];"
                 : "=r"(r[0]), "=r"(r[1]) : "r"(addr));
}
__device__ __forceinline__ void mma16816(float c[4], const u32 a[4], const u32 b[2]) {
    asm volatile("mma.sync.aligned.m16n8k16.row.col.f32.bf16.bf16.f32 "
                 "{%0,%1,%2,%3}, {%4,%5,%6,%7}, {%8,%9}, {%0,%1,%2,%3};"
                 : "+f"(c[0]), "+f"(c[1]), "+f"(c[2]), "+f"(c[3])
                 : "r"(a[0]), "r"(a[1]), "r"(a[2]), "r"(a[3]),
                   "r"(b[0]), "r"(b[1]));
}

// ---------------------------------------------------------------------------
__global__ void init_h_tc(const float* __restrict__ hidden) {
    int idx = blockIdx.x * 256 + threadIdx.x;   // 65536
    if (idx == 0) { g_barcnt = 0; g_bargen = 0; }
    int b = idx >> 10, u = idx & 1023;
    float v = hidden[idx];
    g_hF[0][idx] = v;
    __nv_bfloat16 hi = __float2bfloat16(v);
    __nv_bfloat16 lo = __float2bfloat16(v - __bfloat162float(hi));
    g_Hbf[0][0][b][u] = *(u16*)&hi;
    g_Hbf[0][1][b][u] = *(u16*)&lo;
}

// U^T per-block rows: g_Ubf[((g*2+p)*24 + n)*1024 + k], n = gate*8 + ul
__global__ void uprep_bf(const float* __restrict__ U) {
    size_t idx = (size_t)blockIdx.x * 256 + threadIdx.x;  // 6,291,456
    int k = idx & 1023;
    int rest = (int)(idx >> 10);
    int n = rest % 24;
    int gp = rest / 24;
    int p = gp & 1, g = gp >> 1;
    int s = n >> 3, ul = n & 7;
    float v = U[(size_t)k * U3_ + s * UNITS_ + g * 8 + ul];
    __nv_bfloat16 hi = __float2bfloat16(v);
    __nv_bfloat16 w = p ? __float2bfloat16(v - __bfloat162float(hi)) : hi;
    g_Ubf[idx] = *(u16*)&w;
}

// W -> bf16 hi/lo, k-major per n: g_Wbf[(p*3072+n)*256+k]
__global__ void wprep_bf(const float* __restrict__ W) {
    int gid = blockIdx.x * 256 + threadIdx.x;   // 1,572,864
    int k = gid & 255;
    int n = (gid >> 8) % U3_;
    int p = gid / (U3_ * 256);
    float v = W[(size_t)k * U3_ + n];
    __nv_bfloat16 hi = __float2bfloat16(v);
    __nv_bfloat16 w = p ? __float2bfloat16(v - __bfloat162float(hi)) : hi;
    g_Wbf[gid] = *(u16*)&w;
}

// gathered embedding -> bf16 hi/lo, m' = t*64+b: g_Ebf[(p*8192+m)*256+k]
__global__ void embprep_bf(const int* __restrict__ x,
                           const float* __restrict__ E) {
    int gid = blockIdx.x * 256 + threadIdx.x;   // 2,097,152
    int k = gid & 255, m = gid >> 8;
    int b = m & 63, t = m >> 6;
    float v = E[(size_t)x[b * T_ + t] * EMB_ + k];
    __nv_bfloat16 hi = __float2bfloat16(v);
    __nv_bfloat16 lo = __float2bfloat16(v - __bfloat162float(hi));
    g_Ebf[gid] = *(u16*)&hi;
    g_Ebf[(size_t)M_ * EMB_ + gid] = *(u16*)&lo;
}

// ---------------------------------------------------------------------------
// Phase A (tensor): xin = emb @ W + b0 via split-bf16 mma.sync.
// Grid (24 n-tiles, 64 m-tiles) x 256 thr. Warp (wm=w>>2, wn=w&3):
// m64 x n32 per warp. K chunks of 64 (4 chunks), double-buffered.
// ---------------------------------------------------------------------------
__global__ void __launch_bounds__(256, 1)
xin_mma(const float* __restrict__ bias) {
    extern __shared__ char sm[];
    const u32 sb = s2u(sm);
    const int tid = threadIdx.x;
    const int w = tid >> 5, lane = tid & 31;
    const int wm = w >> 2, wn = w & 3;
    const int nt0 = blockIdx.x * 128;
    const int mt0 = blockIdx.y * 128;

    float acc[4][4][4];
#pragma unroll
    for (int a = 0; a < 4; a++)
#pragma unroll
        for (int b = 0; b < 4; b++)
#pragma unroll
            for (int c = 0; c < 4; c++) acc[a][b][c] = 0.0f;

    const char* ebase = (const char*)g_Ebf;
    const char* wbase = (const char*)g_Wbf;

#define STAGE_A(cc, buf)                                                      \
    do {                                                                      \
        const int c_ = (cc);                                                  \
        const u32 d0 = sb + (buf) * ABUF;                                     \
        _Pragma("unroll")                                                     \
        for (int j = 0; j < 8; j++) {                                         \
            int o = tid + j * 256;                                            \
            int p = o >> 10, row = (o >> 3) & 127, seg = o & 7;               \
            cpa_cg(d0 + (p * 128 + row) * 144 + seg * 16,                     \
                   ebase + ((size_t)(p * M_ + mt0 + row)) * 512 +             \
                       c_ * 128 + seg * 16);                                  \
        }                                                                     \
        _Pragma("unroll")                                                     \
        for (int j = 0; j < 8; j++) {                                         \
            int o = tid + j * 256;                                            \
            int p = o >> 10, row = (o >> 3) & 127, seg = o & 7;               \
            cpa_cg(d0 + 36864 + (p * 128 + row) * 144 + seg * 16,             \
                   wbase + ((size_t)(p * U3_ + nt0 + row)) * 512 +            \
                       c_ * 128 + seg * 16);                                  \
        }                                                                     \
        asm volatile("cp.async.commit_group;");                               \
    } while (0)

    STAGE_A(0, 0);

    const u32 a_off = (u32)((wm * 64 + (lane & 15)) * 144 + (lane >> 4) * 16);
    const u32 b_off = (u32)(36864 + (wn * 32 + (lane >> 4) * 8 + (lane & 7)) * 144 +
                            ((lane >> 3) & 1) * 16);

    for (int c = 0; c < 4; c++) {
        if (c < 3) {
            asm volatile("cp.async.wait_group 0;");
            __syncthreads();
            STAGE_A(c + 1, (c + 1) & 1);
        } else {
            asm volatile("cp.async.wait_group 0;");
            __syncthreads();
        }
        const u32 d0 = sb + (c & 1) * ABUF;
#pragma unroll
        for (int ks = 0; ks < 4; ks++) {
            u32 ah[4][4], al[4][4], bh[2][4], bl[2][4];
#pragma unroll
            for (int ms = 0; ms < 4; ms++) {
                ldmx4(d0 + a_off + ms * 16 * 144 + ks * 32, ah[ms]);
                ldmx4(d0 + a_off + (128 + ms * 16) * 144 + ks * 32, al[ms]);
            }
#pragma unroll
            for (int np = 0; np < 2; np++) {
                ldmx4(d0 + b_off + np * 16 * 144 + ks * 32, bh[np]);
                ldmx4(d0 + b_off + (128 + np * 16) * 144 + ks * 32, bl[np]);
            }
#pragma unroll
            for (int ms = 0; ms < 4; ms++)
#pragma unroll
                for (int np = 0; np < 2; np++)
#pragma unroll
                    for (int hf = 0; hf < 2; hf++) {
                        float* ac = acc[ms][np * 2 + hf];
                        mma16816(ac, ah[ms], bh[np] + hf * 2);
                        mma16816(ac, ah[ms], bl[np] + hf * 2);
                        mma16816(ac, al[ms], bh[np] + hf * 2);
                    }
        }
        __syncthreads();
    }
#undef STAGE_A

    // epilogue: write xin + bias
    float bn[4][2];
#pragma unroll
    for (int ns = 0; ns < 4; ns++)
#pragma unroll
        for (int j = 0; j < 2; j++)
            bn[ns][j] = bias[nt0 + wn * 32 + ns * 8 + 2 * (lane & 3) + j];

#pragma unroll
    for (int ms = 0; ms < 4; ms++)
#pragma unroll
        for (int ns = 0; ns < 4; ns++)
#pragma unroll
            for (int i = 0; i < 2; i++)
#pragma unroll
                for (int j = 0; j < 2; j++) {
                    int m = mt0 + wm * 64 + ms * 16 + (lane >> 2) + 8 * i;
                    int n = nt0 + wn * 32 + ns * 8 + 2 * (lane & 3) + j;
                    g_xin[(size_t)m * U3_ + n] = acc[ms][ns][2 * i + j] + bn[ns][j];
                }
}

// ---------------------------------------------------------------------------
// Persistent scan: 128 blocks x 256 thr, 1 block/SM. Block g owns 8 units.
// U resident in smem. Warp w: mt=w&3 (16 batches), gr=w>>2 (k-half).
// 3-buffer H staging, one sync/chunk; split epilogue across gr groups.
// ---------------------------------------------------------------------------
__global__ void __launch_bounds__(256, 1)
gru_scan(const float* __restrict__ bias, float* __restrict__ out) {
    extern __shared__ char sm[];
    const u32 sb = s2u(sm);
    const int tid = threadIdx.x;
    const int w = tid >> 5, lane = tid & 31;
    const int mt = w & 3, gr = w >> 2;
    const int g = blockIdx.x;

    // ---- stage U slice once ----
    {
        const char* usrc = (const char*)g_Ubf + (size_t)g * 98304;
#pragma unroll
        for (int j = 0; j < 24; j++) {
            int o = tid + j * 256;
            int row = o >> 7, seg = o & 127;
            cpa_ca(sb + row * USTR + seg * 16, usrc + (size_t)o * 16);
        }
        asm volatile("cp.async.commit_group;");
    }

    const u32 a_off = (u32)((mt * 16 + (lane & 15)) * 144 + (lane >> 4) * 16);
    const u32 b01 = sb + (u32)(((lane >> 4) * 8 + (lane & 7)) * USTR +
                               ((lane >> 3) & 1) * 16);
    const u32 b2  = sb + (u32)((16 + (lane & 7)) * USTR + ((lane >> 3) & 1) * 16);

    const int u0e = g * 8 + 2 * (lane & 3);
    const int b_e = mt * 16 + (lane >> 2) + 8 * gr;   // this group's batch
    const float bz0 = bias[U3_ + u0e],              bz1 = bias[U3_ + u0e + 1];
    const float br0 = bias[U3_ + UNITS_ + u0e],     br1 = bias[U3_ + UNITS_ + u0e + 1];
    const float bh0 = bias[U3_ + 2 * UNITS_ + u0e], bh1 = bias[U3_ + 2 * UNITS_ + u0e + 1];

    float* red = (float*)(sm + REDOFF);

    for (int t = 0; t < T_; t++) {
        const int cur = t & 1, nxt = cur ^ 1;
        const char* hsrc = (const char*)&g_Hbf[cur][0][0][0];

        // prefetch epilogue operands (hidden behind chunk loop)
        const float* xrow = &g_xin[(size_t)(t * 64 + b_e) * U3_ + u0e];
        float xz0 = __ldg(xrow), xz1 = __ldg(xrow + 1);
        float xr0 = __ldg(xrow + UNITS_), xr1 = __ldg(xrow + UNITS_ + 1);
        float xh0 = __ldg(xrow + 2 * UNITS_), xh1 = __ldg(xrow + 2 * UNITS_ + 1);
        float hp0 = g_hF[cur][b_e * UNITS_ + u0e];
        float hp1 = g_hF[cur][b_e * UNITS_ + u0e + 1];

        float acc[3][4];
#pragma unroll
        for (int i = 0; i < 3; i++)
#pragma unroll
            for (int j = 0; j < 4; j++) acc[i][j] = 0.0f;

#define STAGE_H(cc, buf)                                                      \
    do {                                                                      \
        _Pragma("unroll")                                                     \
        for (int j = 0; j < 8; j++) {                                         \
            int o = tid + j * 256;                                            \
            int grs = o >> 10, r = (o >> 3) & 127, seg = o & 7;               \
            int cab = grs * 8 + (cc);                                         \
            cpa_cg(sb + HOFF + (grs * 3 + (buf)) * HSZ + r * 144 + seg * 16,  \
                   hsrc + ((size_t)r * 1024 + cab * 64) * 2 + seg * 16);      \
        }                                                                     \
        asm volatile("cp.async.commit_group;");                               \
    } while (0)

        STAGE_H(0, 0);
        STAGE_H(1, 1);

        for (int c = 0; c < 8; c++) {
            if (c < 7) asm volatile("cp.async.wait_group 1;");
            else       asm volatile("cp.async.wait_group 0;");
            __syncthreads();
            if (c < 6) STAGE_H(c + 2, (c + 2) % 3);

            const int cab = gr * 8 + c;
            const u32 abase = sb + HOFF + (u32)((gr * 3 + c % 3) * HSZ) + a_off;
            const u32 koff = (u32)(cab * 128);
#pragma unroll
            for (int ks = 0; ks < 4; ks++) {
                u32 ah[4], al[4], b4h[4], b4l[4], b2h[2], b2l[2];
                const u32 ko = koff + ks * 32;
                ldmx4(abase + ks * 32, ah);
                ldmx4(abase + 9216 + ks * 32, al);
                ldmx4(b01 + ko, b4h);
                ldmx4(b01 + 24 * USTR + ko, b4l);
                ldmx2(b2 + ko, b2h);
                ldmx2(b2 + 24 * USTR + ko, b2l);
                mma16816(acc[0], ah, b4h);     mma16816(acc[1], ah, b4h + 2);
                mma16816(acc[2], ah, b2h);
                mma16816(acc[0], ah, b4l);     mma16816(acc[1], ah, b4l + 2);
                mma16816(acc[2], ah, b2l);
                mma16816(acc[0], al, b4h);     mma16816(acc[1], al, b4h + 2);
                mma16816(acc[2], al, b2h);
            }
        }
#undef STAGE_H

        // ---- symmetric partial exchange: each group dumps the OTHER half ----
        const int oi = gr ^ 1;
#pragma unroll
        for (int i = 0; i < 3; i++)
#pragma unroll
            for (int j = 0; j < 2; j++)
                red[(w * 32 + lane) * 6 + i * 2 + j] = acc[i][2 * oi + j];
        __syncthreads();
        const int pw = (gr ^ 1) * 4 + mt;
#pragma unroll
        for (int i = 0; i < 3; i++)
#pragma unroll
            for (int j = 0; j < 2; j++)
                acc[i][2 * gr + j] += red[(pw * 32 + lane) * 6 + i * 2 + j];

        // ---- epilogue: this group's batch half (i = gr) ----
#pragma unroll
        for (int j = 0; j < 2; j++) {
            const int u = u0e + j;
            const int r = 2 * gr + j;
            const float xz = j ? xz1 : xz0, xr = j ? xr1 : xr0, xh = j ? xh1 : xh0;
            const float hprev = j ? hp1 : hp0;
            const float bz_ = j ? bz1 : bz0, br_ = j ? br1 : br0, bh_ = j ? bh1 : bh0;

            float z = 1.f / (1.f + expf(-(xz + acc[0][r] + bz_)));
            float rr = 1.f / (1.f + expf(-(xr + acc[1][r] + br_)));
            float hh = tanhf(xh + rr * (acc[2][r] + bh_));
            float hn = z * hprev + (1.f - z) * hh;

            g_hF[nxt][b_e * UNITS_ + u] = hn;
            out[(size_t)(b_e * T_ + t) * UNITS_ + u] = hn;
            __nv_bfloat16 hi = __float2bfloat16(hn);
            __nv_bfloat16 lo = __float2bfloat16(hn - __bfloat162float(hi));
            g_Hbf[nxt][0][b_e][u] = *(u16*)&hi;
            g_Hbf[nxt][1][b_e][u] = *(u16*)&lo;
            if (t == T_ - 1)
                out[(size_t)M_ * UNITS_ + (size_t)b_e * UNITS_ + u] = hn;
        }

        // ---- grid-wide barrier ----
        __threadfence();
        __syncthreads();
        if (tid == 0) {
            unsigned old = atomicAdd(&g_barcnt, 1);
            if (old == NBLK2 - 1) {
                g_barcnt = 0;
                __threadfence();
                atomicAdd(&g_bargen, 1);
            } else {
                unsigned v;
                do {
                    asm volatile("ld.acquire.gpu.global.u32 %0, [%1];"
                                 : "=r"(v) : "l"(&g_bargen));
                } while (v < (unsigned)(t + 1));
            }
        }
        __syncthreads();
    }
}

extern "C" void kernel_launch(void* const* d_in, const int* in_sizes, int n_in,
                              void* d_out, int out_size) {
    const int*   x      = (const int*)d_in[0];
    const float* hidden = (const float*)d_in[1];
    const float* E      = (const float*)d_in[2];
    const float* W      = (const float*)d_in[3];
    const float* Umat   = (const float*)d_in[4];
    const float* bias   = (const float*)d_in[5];
    float* out = (float*)d_out;

    cudaFuncSetAttribute(gru_scan,
                         cudaFuncAttributeMaxDynamicSharedMemorySize, SMEMSZ);
    cudaFuncSetAttribute(xin_mma,
                         cudaFuncAttributeMaxDynamicSharedMemorySize, SMEMA);

    init_h_tc<<<256, 256>>>(hidden);
    uprep_bf<<<24576, 256>>>(Umat);
    wprep_bf<<<6144, 256>>>(W);
    embprep_bf<<<8192, 256>>>(x, E);

    dim3 gridA(U3_ / 128, M_ / 128);   // (24, 64)
    xin_mma<<<gridA, 256, SMEMA>>>(bias);

    gru_scan<<<NBLK2, 256, SMEMSZ>>>(bias, out);
}